// round 16
// baseline (speedup 1.0000x reference)
#include <cuda_runtime.h>
#include <cuda_bf16.h>
#include <cooperative_groups.h>

namespace cg = cooperative_groups;

// ---------------------------------------------------------------------------
// Fused persistent kernel: 128 blocks = 32 clusters of 4, ONE cluster sync,
// ONE grid sync (arrive-only for blocks with no post-sync work).
// R13 contraction-split structure + R15 parallel argmin.
// Only feat[0:64] is live (winner in -1..63) -> 500K-row MLP collapses to 64.
//
// Cluster cid = b>>2 owns rows r0=2*cid, r1=r0+1; rank q = b&3:
//   - winner table: 64 rows x 4 j-slices, shfl lexicographic argmin
//   - MLP: L1,L2 redundant; L3 computes gf QUARTER (W3/4) -- local only
//   - partial ts over ALL 256 cols from own gf quarter (Wn1 row-slice /4)
//   - cluster.sync; all-reduce 4 partials (fixed order) + bn1 + relu -> ts
//   - y quarter = ts @ Wn2[:,quarter] + bn2 -> g_y   (Wn2/4)
// arrive (all 128); blocks 4-127 exit; blocks 0-3 wait then:
//   - agg = mean(g_y); head k=b -> out[k]
// ---------------------------------------------------------------------------

#define G   64
#define NB  128

__device__ float g_y[G * 256];
__device__ unsigned long long g_ctr;   // monotonic across launches/replays

struct SmemLayout {
    float  gf[2 * 256];     // gf rows (only own quarter valid)
    float  ts[2 * 256];     // full ts rows after all-reduce (agg in heads)
    float  tsp[2 * 256];    // own partial ts (peer-readable)
    float4 sp4[512];        // chunk partials
    float  ps[192];
    float  gs[192];
    float  h1[2 * 64];
    float  h2[2 * 128];
    float  p[8];
    float  h1s[128];
    int    si[G];
    int    sw[4];
};

__global__ void __launch_bounds__(256, 1) __cluster_dims__(4, 1, 1)
fused_kernel(const float* __restrict__ pos, const float* __restrict__ gp,
             const float* __restrict__ W1,  const float* __restrict__ b1,
             const float* __restrict__ W2,  const float* __restrict__ b2,
             const float* __restrict__ W3,  const float* __restrict__ b3,
             const float* __restrict__ Wn1, const float* __restrict__ bn1,
             const float* __restrict__ Wn2, const float* __restrict__ bn2,
             const float* __restrict__ Wh1, const float* __restrict__ bh1,
             const float* __restrict__ Wh2, const float* __restrict__ bh2,
             float* __restrict__ out)
{
    __shared__ SmemLayout sm;
    const int b = blockIdx.x;
    const int t = threadIdx.x;
    cg::cluster_group cluster = cg::this_cluster();
    const int q   = b & 3;             // rank: gf/contraction quarter + y quarter
    const int cid = b >> 2;            // cluster id
    const int r0  = cid * 2;
    const int r1  = r0 + 1;

    // ---- winner table (redundant per block; 4 j-slices per row) ----
    if (t < G * 3) { sm.ps[t] = pos[t]; sm.gs[t] = gp[t]; }
    __syncthreads();
    {
        const int row = t >> 2;                    // 0..63
        const int sl  = t & 3;                     // j-slice
        const float px = sm.ps[row * 3], py = sm.ps[row * 3 + 1], pz = sm.ps[row * 3 + 2];
        float best = 3.4e38f; int bj = sl * 16;
        #pragma unroll 4
        for (int j = sl * 16; j < sl * 16 + 16; j++) {
            float dx = px - sm.gs[j * 3];
            float dy = py - sm.gs[j * 3 + 1];
            float dz = pz - sm.gs[j * 3 + 2];
            float d  = dx * dx + dy * dy + dz * dz;
            if (d < best) { best = d; bj = j; }    // first idx wins within slice
        }
        // lexicographic (d, j) reduce over the 4 slices: argmin, first idx on ties
        #pragma unroll
        for (int off = 1; off < 4; off <<= 1) {
            float od = __shfl_down_sync(0xffffffffu, best, off, 4);
            int   oj = __shfl_down_sync(0xffffffffu, bj,   off, 4);
            if (od < best || (od == best && oj < bj)) { best = od; bj = oj; }
        }
        if (sl == 0) sm.si[row] = bj;
    }
    __syncthreads();
    if (t < G) {
        int c0 = (sm.si[t] == r0) ? t : -1;
        int c1 = (sm.si[t] == r1) ? t : -1;
        #pragma unroll
        for (int off = 16; off; off >>= 1) {
            c0 = max(c0, __shfl_xor_sync(0xffffffffu, c0, off));
            c1 = max(c1, __shfl_xor_sync(0xffffffffu, c1, off));
        }
        if ((t & 31) == 0) { sm.sw[t >> 5] = c0; sm.sw[2 + (t >> 5)] = c1; }
    }
    __syncthreads();
    const int w0 = max(sm.sw[0], sm.sw[1]);
    const int w1 = max(sm.sw[2], sm.sw[3]);

    // ---- MLP for both rows (clip(winner,0); zero-mask at gf) ----
    if (t < 3) {
        sm.p[t]     = pos[max(w0, 0) * 3 + t];
        sm.p[4 + t] = pos[max(w1, 0) * 3 + t];
    }
    __syncthreads();
    if (t < 64) {       // layer1: 3 -> 64, both rows
        float wa = W1[t], wb = W1[64 + t], wc = W1[128 + t], bb = b1[t];
        sm.h1[t]      = fmaxf(bb + sm.p[0] * wa + sm.p[1] * wb + sm.p[2] * wc, 0.0f);
        sm.h1[64 + t] = fmaxf(bb + sm.p[4] * wa + sm.p[5] * wb + sm.p[6] * wc, 0.0f);
    }
    __syncthreads();
    {   // layer2: 64 -> 128, both rows; 32 float4 col-groups, 8 chunks x 8 k
        const float4* W = (const float4*)W2;        // [64][32]
        const int c  = t & 31;
        const int ch = t >> 5;
        float4 a0 = {0,0,0,0}, a1 = {0,0,0,0};
        #pragma unroll
        for (int j = 0; j < 8; j++) {
            int k = ch * 8 + j;
            float4 wv = W[k * 32 + c];
            float  x0 = sm.h1[k], x1 = sm.h1[64 + k];
            a0.x = fmaf(x0, wv.x, a0.x); a0.y = fmaf(x0, wv.y, a0.y);
            a0.z = fmaf(x0, wv.z, a0.z); a0.w = fmaf(x0, wv.w, a0.w);
            a1.x = fmaf(x1, wv.x, a1.x); a1.y = fmaf(x1, wv.y, a1.y);
            a1.z = fmaf(x1, wv.z, a1.z); a1.w = fmaf(x1, wv.w, a1.w);
        }
        sm.sp4[ch * 32 + c]       = a0;
        sm.sp4[256 + ch * 32 + c] = a1;
    }
    __syncthreads();
    if (t < 64) {       // combine layer2: (row, col-group)
        const int row = t >> 5;
        const int c   = t & 31;
        float4 a = sm.sp4[row * 256 + c];
        #pragma unroll
        for (int s = 1; s < 8; s++) {
            float4 v = sm.sp4[row * 256 + s * 32 + c];
            a.x += v.x; a.y += v.y; a.z += v.z; a.w += v.w;
        }
        const int o = c * 4;
        float4 bb = *(const float4*)(b2 + o);
        float* dst = sm.h2 + row * 128 + o;
        dst[0] = fmaxf(a.x + bb.x, 0.0f);
        dst[1] = fmaxf(a.y + bb.y, 0.0f);
        dst[2] = fmaxf(a.z + bb.z, 0.0f);
        dst[3] = fmaxf(a.w + bb.w, 0.0f);
    }
    __syncthreads();
    {   // layer3 QUARTER: 64 cols of gf, both rows; 16 groups, 16 chunks x 8 k
        const float4* W = (const float4*)W3;        // [128][64]
        const int c  = t & 15;
        const int ch = t >> 4;
        float4 a0 = {0,0,0,0}, a1 = {0,0,0,0};
        #pragma unroll
        for (int j = 0; j < 8; j++) {
            int k = ch * 8 + j;
            float4 wv = W[k * 64 + q * 16 + c];
            float  x0 = sm.h2[k], x1 = sm.h2[128 + k];
            a0.x = fmaf(x0, wv.x, a0.x); a0.y = fmaf(x0, wv.y, a0.y);
            a0.z = fmaf(x0, wv.z, a0.z); a0.w = fmaf(x0, wv.w, a0.w);
            a1.x = fmaf(x1, wv.x, a1.x); a1.y = fmaf(x1, wv.y, a1.y);
            a1.z = fmaf(x1, wv.z, a1.z); a1.w = fmaf(x1, wv.w, a1.w);
        }
        sm.sp4[ch * 16 + c]       = a0;
        sm.sp4[256 + ch * 16 + c] = a1;
    }
    __syncthreads();
    if (t < 32) {       // combine gf quarter (stored at its global offset)
        const int row = t >> 4;
        const int c   = t & 15;
        float4 a = sm.sp4[row * 256 + c];
        #pragma unroll
        for (int s = 1; s < 16; s++) {
            float4 v = sm.sp4[row * 256 + s * 16 + c];
            a.x += v.x; a.y += v.y; a.z += v.z; a.w += v.w;
        }
        const int o = q * 64 + c * 4;
        float4 bb = *(const float4*)(b3 + o);
        const int wr = row ? w1 : w0;
        const float m = (wr >= 0) ? 1.0f : 0.0f;
        float* dst = sm.gf + row * 256 + o;
        dst[0] = (a.x + bb.x) * m;
        dst[1] = (a.y + bb.y) * m;
        dst[2] = (a.z + bb.z) * m;
        dst[3] = (a.w + bb.w) * m;
    }
    __syncthreads();

    // ---- PARTIAL ts over ALL 256 cols from own gf quarter ----
    // contraction slice k in [64q, 64q+64); reads Wn1 row-slice (64 KB)
    {
        const float4* W = (const float4*)Wn1;       // [256][64]
        const int c  = t & 63;                      // full col-group range
        const int ch = t >> 6;                      // 4 chunks x 16 k
        float4 a0 = {0,0,0,0}, a1 = {0,0,0,0};
        #pragma unroll
        for (int j = 0; j < 16; j++) {
            const int k = q * 64 + ch * 16 + j;     // global k in own quarter
            float4 wv = W[k * 64 + c];
            float  x0 = sm.gf[k], x1 = sm.gf[256 + k];
            a0.x = fmaf(x0, wv.x, a0.x); a0.y = fmaf(x0, wv.y, a0.y);
            a0.z = fmaf(x0, wv.z, a0.z); a0.w = fmaf(x0, wv.w, a0.w);
            a1.x = fmaf(x1, wv.x, a1.x); a1.y = fmaf(x1, wv.y, a1.y);
            a1.z = fmaf(x1, wv.z, a1.z); a1.w = fmaf(x1, wv.w, a1.w);
        }
        sm.sp4[ch * 64 + c]       = a0;
        sm.sp4[256 + ch * 64 + c] = a1;
    }
    __syncthreads();
    if (t < 128) {      // combine 4 chunk-partials -> tsp (own partial ts)
        const int row = t >> 6;
        const int c   = t & 63;
        float4 a = sm.sp4[row * 256 + c];
        #pragma unroll
        for (int s = 1; s < 4; s++) {
            float4 v = sm.sp4[row * 256 + s * 64 + c];
            a.x += v.x; a.y += v.y; a.z += v.z; a.w += v.w;
        }
        ((float4*)sm.tsp)[row * 64 + c] = a;
    }
    __syncthreads();

    // ---- ONE cluster sync; all-reduce 4 rank partials (fixed order) ----
    cluster.sync();
    if (t < 128) {
        const int row = t >> 6;
        const int c   = t & 63;
        const int idx = row * 64 + c;
        float4 a = {0,0,0,0};
        #pragma unroll
        for (int rr = 0; rr < 4; rr++) {            // fixed rank order 0..3
            const float4* src = (const float4*)cluster.map_shared_rank((const void*)sm.tsp, rr);
            const float4 v = src[idx];
            a.x += v.x; a.y += v.y; a.z += v.z; a.w += v.w;
        }
        const int o = c * 4;
        const float4 bb = *(const float4*)(bn1 + o);
        float* dst = sm.ts + row * 256 + o;
        dst[0] = fmaxf(a.x + bb.x, 0.0f);
        dst[1] = fmaxf(a.y + bb.y, 0.0f);
        dst[2] = fmaxf(a.z + bb.z, 0.0f);
        dst[3] = fmaxf(a.w + bb.w, 0.0f);
    }
    __syncthreads();

    // ---- y quarter: ts @ Wn2[:,quarter] + bn2 -> g_y, both rows ----
    {
        const float4* W = (const float4*)Wn2;
        const int c  = t & 15;
        const int ch = t >> 4;                      // 16 chunks x 16 k
        float4 a0 = {0,0,0,0}, a1 = {0,0,0,0};
        #pragma unroll
        for (int j = 0; j < 16; j++) {
            int k = ch * 16 + j;
            float4 wv = W[k * 64 + q * 16 + c];
            float  x0 = sm.ts[k], x1 = sm.ts[256 + k];
            a0.x = fmaf(x0, wv.x, a0.x); a0.y = fmaf(x0, wv.y, a0.y);
            a0.z = fmaf(x0, wv.z, a0.z); a0.w = fmaf(x0, wv.w, a0.w);
            a1.x = fmaf(x1, wv.x, a1.x); a1.y = fmaf(x1, wv.y, a1.y);
            a1.z = fmaf(x1, wv.z, a1.z); a1.w = fmaf(x1, wv.w, a1.w);
        }
        sm.sp4[ch * 16 + c]       = a0;
        sm.sp4[256 + ch * 16 + c] = a1;
    }
    __syncthreads();
    if (t < 32) {
        const int row = t >> 4;
        const int c   = t & 15;
        float4 a = sm.sp4[row * 256 + c];
        #pragma unroll
        for (int s = 1; s < 16; s++) {
            float4 v = sm.sp4[row * 256 + s * 16 + c];
            a.x += v.x; a.y += v.y; a.z += v.z; a.w += v.w;
        }
        const int o = q * 64 + c * 4;
        float4 bb = *(const float4*)(bn2 + o);
        const int r = row ? r1 : r0;
        float4 v = make_float4(a.x + bb.x, a.y + bb.y, a.z + bb.z, a.w + bb.w);
        *(float4*)(g_y + r * 256 + o) = v;
    }

    // ---- grid sync: all arrive; only blocks 0-3 wait ----
    __syncthreads();                    // g_y writes complete block-wide
    if (b >= 4) {
        if (t == 0) {
            __threadfence();            // publish g_y before arrival
            atomicAdd(&g_ctr, 1ULL);
        }
        return;                         // 124 blocks retire immediately
    }
    if (t == 0) {
        __threadfence();
        unsigned long long ticket = atomicAdd(&g_ctr, 1ULL) + 1ULL;
        unsigned long long target = ((ticket + (NB - 1)) / NB) * (unsigned long long)NB;
        volatile unsigned long long* pctr = (volatile unsigned long long*)&g_ctr;
        while (*pctr < target) { }
        __threadfence();
    }
    __syncthreads();

    // ================= Heads: blocks 0-3, head k = b =================
    {
        const int k = b;
        float* agg = sm.ts;                 // reuse as agg[256]
        float* pfl = (float*)sm.sp4;
        {   // agg = mean over 64 rows of g_y
            const float4* Y = (const float4*)g_y;   // [64][64]
            const int c  = t & 63;
            const int rc = t >> 6;
            float4 a = {0,0,0,0};
            #pragma unroll
            for (int j = 0; j < 16; j++) {
                float4 v = Y[(rc * 16 + j) * 64 + c];
                a.x += v.x; a.y += v.y; a.z += v.z; a.w += v.w;
            }
            sm.sp4[rc * 64 + c] = a;
        }
        __syncthreads();
        agg[t] = (pfl[t] + pfl[256 + t] + pfl[512 + t] + pfl[768 + t]) * (1.0f / 64.0f);
        __syncthreads();

        {   // z = agg @ Wh1[k]: 32 float4 d-groups x 8 c-slices
            const int dg   = t & 31;
            const int half = t >> 5;
            const float* Wb = Wh1 + k * 32768 + dg * 4;
            float4 acc = {0,0,0,0};
            const int c0 = half * 32;
            #pragma unroll
            for (int c2 = c0; c2 < c0 + 32; c2++) {
                const float  av = agg[c2];
                const float4 wv = *(const float4*)(Wb + c2 * 128);
                acc.x = fmaf(av, wv.x, acc.x); acc.y = fmaf(av, wv.y, acc.y);
                acc.z = fmaf(av, wv.z, acc.z); acc.w = fmaf(av, wv.w, acc.w);
            }
            sm.sp4[t] = acc;
        }
        __syncthreads();
        if (t < 32) {
            float4 a = sm.sp4[t];
            #pragma unroll
            for (int s = 1; s < 8; s++) {
                const float4 v = sm.sp4[t + 32 * s];
                a.x += v.x; a.y += v.y; a.z += v.z; a.w += v.w;
            }
            const int o = t * 4;
            sm.h1s[o + 0] = fmaxf(a.x + bh1[k * 128 + o + 0], 0.0f);
            sm.h1s[o + 1] = fmaxf(a.y + bh1[k * 128 + o + 1], 0.0f);
            sm.h1s[o + 2] = fmaxf(a.z + bh1[k * 128 + o + 2], 0.0f);
            sm.h1s[o + 3] = fmaxf(a.w + bh1[k * 128 + o + 3], 0.0f);
        }
        __syncthreads();
        if (t < 32) {
            float a = 0.0f;
            #pragma unroll
            for (int j = t; j < 128; j += 32)
                a = fmaf(sm.h1s[j], Wh2[k * 128 + j], a);
            #pragma unroll
            for (int off = 16; off; off >>= 1)
                a += __shfl_xor_sync(0xffffffffu, a, off);
            if (t == 0) out[k] = a + bh2[k];
        }
    }
}

extern "C" void kernel_launch(void* const* d_in, const int* in_sizes, int n_in,
                              void* d_out, int out_size)
{
    const float* positions = (const float*)d_in[0];
    const float* grid_pts  = (const float*)d_in[1];
    const float* W1  = (const float*)d_in[2];
    const float* b1  = (const float*)d_in[3];
    const float* W2  = (const float*)d_in[4];
    const float* b2  = (const float*)d_in[5];
    const float* W3  = (const float*)d_in[6];
    const float* b3  = (const float*)d_in[7];
    const float* Wn1 = (const float*)d_in[8];
    const float* bn1 = (const float*)d_in[9];
    const float* Wn2 = (const float*)d_in[10];
    const float* bn2 = (const float*)d_in[11];
    const float* Wh1 = (const float*)d_in[12];
    const float* bh1 = (const float*)d_in[13];
    const float* Wh2 = (const float*)d_in[14];
    const float* bh2 = (const float*)d_in[15];
    float* out = (float*)d_out;

    fused_kernel<<<NB, 256>>>(positions, grid_pts, W1, b1, W2, b2, W3, b3,
                              Wn1, bn1, Wn2, bn2, Wh1, bh1, Wh2, bh2, out);
}